// round 5
// baseline (speedup 1.0000x reference)
#include <cuda_runtime.h>
#include <cuda_bf16.h>
#include <cstdint>

#define NB 8
#define NC 192
#define NH 128
#define NW 128
#define HWP (NH*NW)            // 16384 pixels per plane
#define NPIX (NB*HWP)          // 131072
#define NELEM ((size_t)NB*NC*HWP) // 25,165,824
#define NHEADS 4
#define SDIM 48                // channels per head
#define NSPLIT 64              // t-splits for K^T Q reduction

// ---------------- scratch (device globals; no runtime allocation) -------------
__device__ float g_xn[NB*NC*HWP];
__device__ float g_qp[NB*NC*HWP];
__device__ float g_kp[NB*NC*HWP];
__device__ float g_vp[NB*NC*HWP];
__device__ float g_q [NB*NC*HWP];
__device__ float g_k [NB*NC*HWP];
__device__ float g_v [NB*NC*HWP];
__device__ float g_oc[NB*NC*HWP];
__device__ float g_z [NB*NC*HWP];
__device__ float g_spart[(size_t)NSPLIT*NB*NHEADS*SDIM*SDIM];
__device__ float g_att[(size_t)NB*NHEADS*SDIM*SDIM];

// ---------------- 1) channel LayerNorm (per pixel over C=192), fp32 ----------
__global__ void ln_kernel(const float* __restrict__ x,
                          const float* __restrict__ lw,
                          const float* __restrict__ lb,
                          float* __restrict__ xn)
{
    int pix = blockIdx.x * blockDim.x + threadIdx.x;   // 0..NPIX-1
    int b = pix / HWP;
    int p = pix - b * HWP;
    const float* xb = x + (size_t)b * NC * HWP + p;
    float s = 0.f, s2 = 0.f;
    #pragma unroll 4
    for (int c = 0; c < NC; c++) {
        float v = __ldg(xb + (size_t)c * HWP);
        s += v; s2 += v * v;
    }
    const float inv_c = 1.0f / NC;
    float mu = s * inv_c;
    float var = s2 * inv_c - mu * mu;
    float rstd = rsqrtf(var + 1e-5f);
    float* ob = xn + (size_t)b * NC * HWP + p;
    #pragma unroll 4
    for (int c = 0; c < NC; c++) {
        float v = __ldg(xb + (size_t)c * HWP);
        ob[(size_t)c * HWP] = (v - mu) * rstd * __ldg(lw + c) + __ldg(lb + c);
    }
}

// ---------------- 2) pointwise 1x1 conv GEMM (NSETS weight sets share B) -----
// out[set][b, oc, p] = sum_c W[set][oc,c] * xin[b,c,p] + bias[set][oc]
// BM=64 oc, BN=64 pixels, BK=16, 256 threads, 4x4 micro-tile per set.
template<int NSETS>
__global__ __launch_bounds__(256)
void pw_gemm_kernel(const float* __restrict__ xin,
                    const float* __restrict__ w0, const float* __restrict__ bb0, float* __restrict__ o0,
                    const float* __restrict__ w1, const float* __restrict__ bb1, float* __restrict__ o1,
                    const float* __restrict__ w2, const float* __restrict__ bb2, float* __restrict__ o2)
{
    __shared__ float As[NSETS][16][65];
    __shared__ float Bs[16][64];

    const int tid = threadIdx.x;
    const int tx = tid & 15;
    const int ty = tid >> 4;
    const int p0  = blockIdx.x * 64;
    const int oc0 = blockIdx.y * 64;
    const size_t bbase = (size_t)blockIdx.z * NC * HWP;

    const float* wptr[3]  = { w0, w1, w2 };
    const float* bptr[3]  = { bb0, bb1, bb2 };
    float*       optr[3]  = { o0, o1, o2 };

    float acc[NSETS][4][4];
    #pragma unroll
    for (int s = 0; s < NSETS; s++)
        #pragma unroll
        for (int i = 0; i < 4; i++)
            #pragma unroll
            for (int j = 0; j < 4; j++)
                acc[s][i][j] = 0.f;

    for (int k0 = 0; k0 < NC; k0 += 16) {
        // load B tile (xn): 16 x 64
        #pragma unroll
        for (int m = 0; m < 4; m++) {
            int idx = tid + 256 * m;
            int kk = idx >> 6, p = idx & 63;
            Bs[kk][p] = xin[bbase + (size_t)(k0 + kk) * HWP + p0 + p];
        }
        // load A tiles (weights), transposed into [k][oc]
        #pragma unroll
        for (int s = 0; s < NSETS; s++) {
            const float* w = wptr[s];
            #pragma unroll
            for (int m = 0; m < 4; m++) {
                int idx = tid + 256 * m;
                int oc = idx >> 4, kk = idx & 15;
                As[s][kk][oc] = __ldg(w + (size_t)(oc0 + oc) * NC + k0 + kk);
            }
        }
        __syncthreads();

        #pragma unroll
        for (int k = 0; k < 16; k++) {
            float bv[4];
            #pragma unroll
            for (int j = 0; j < 4; j++) bv[j] = Bs[k][tx + 16 * j];
            #pragma unroll
            for (int s = 0; s < NSETS; s++) {
                float av[4];
                #pragma unroll
                for (int i = 0; i < 4; i++) av[i] = As[s][k][ty + 16 * i];
                #pragma unroll
                for (int i = 0; i < 4; i++)
                    #pragma unroll
                    for (int j = 0; j < 4; j++)
                        acc[s][i][j] += av[i] * bv[j];
            }
        }
        __syncthreads();
    }

    #pragma unroll
    for (int s = 0; s < NSETS; s++) {
        #pragma unroll
        for (int i = 0; i < 4; i++) {
            int oc = oc0 + ty + 16 * i;
            float bsv = __ldg(bptr[s] + oc);
            #pragma unroll
            for (int j = 0; j < 4; j++) {
                int p = p0 + tx + 16 * j;
                optr[s][bbase + (size_t)oc * HWP + p] = acc[s][i][j] + bsv;
            }
        }
    }
}

// ---------------- 3) depthwise 3x3 SAME conv + bias (3 tensors fused) --------
__global__ void dw3_kernel(const float* __restrict__ qp, const float* __restrict__ kp, const float* __restrict__ vp,
                           const float* __restrict__ qdw, const float* __restrict__ qdb,
                           const float* __restrict__ kdw, const float* __restrict__ kdb,
                           const float* __restrict__ vdw, const float* __restrict__ vdb,
                           float* __restrict__ qo, float* __restrict__ ko, float* __restrict__ vo)
{
    int plane = blockIdx.y;              // b*NC + c
    int c = plane % NC;
    int p = blockIdx.x * blockDim.x + threadIdx.x;   // 0..HWP-1
    int h = p >> 7, w = p & 127;
    size_t base = (size_t)plane * HWP;

    float aq = __ldg(qdb + c), ak = __ldg(kdb + c), av = __ldg(vdb + c);
    #pragma unroll
    for (int kh = 0; kh < 3; kh++) {
        int hh = h + kh - 1;
        if ((unsigned)hh >= NH) continue;
        #pragma unroll
        for (int kw = 0; kw < 3; kw++) {
            int ww = w + kw - 1;
            if ((unsigned)ww >= NW) continue;
            size_t idx = base + (size_t)hh * NW + ww;
            int wi = c * 9 + kh * 3 + kw;
            aq += __ldg(qp + idx) * __ldg(qdw + wi);
            ak += __ldg(kp + idx) * __ldg(kdw + wi);
            av += __ldg(vp + idx) * __ldg(vdw + wi);
        }
    }
    qo[base + p] = aq;
    ko[base + p] = ak;
    vo[base + p] = av;
}

// ---------------- 4) S partials: S[s,q] = sum_pix K[.,s]*Q[.,q] --------------
// grid.x = NSPLIT (t-splits), grid.y = NB*NHEADS; 256 threads map 16x16 -> 3x3
__global__ __launch_bounds__(256)
void spart_kernel(const float* __restrict__ K, const float* __restrict__ Q,
                  float* __restrict__ spart)
{
    __shared__ float Ks[SDIM][33];
    __shared__ float Qs[SDIM][33];
    int split = blockIdx.x;
    int bh = blockIdx.y;
    int b = bh >> 2, hd = bh & 3;
    size_t cbase = (size_t)b * NC * HWP + (size_t)hd * SDIM * HWP;
    int p0 = split * (HWP / NSPLIT);      // 256 pixels per block

    int tid = threadIdx.x;
    int si0 = (tid >> 4) * 3;
    int qi0 = (tid & 15) * 3;

    float acc[3][3] = {};
    for (int ch = 0; ch < (HWP / NSPLIT) / 32; ch++) {
        int pp = p0 + ch * 32;
        for (int l = tid; l < SDIM * 32; l += 256) {
            int cc = l >> 5, t = l & 31;
            Ks[cc][t] = K[cbase + (size_t)cc * HWP + pp + t];
            Qs[cc][t] = Q[cbase + (size_t)cc * HWP + pp + t];
        }
        __syncthreads();
        #pragma unroll 4
        for (int t = 0; t < 32; t++) {
            float kv[3], qv[3];
            #pragma unroll
            for (int i = 0; i < 3; i++) { kv[i] = Ks[si0 + i][t]; qv[i] = Qs[qi0 + i][t]; }
            #pragma unroll
            for (int i = 0; i < 3; i++)
                #pragma unroll
                for (int j = 0; j < 3; j++)
                    acc[i][j] += kv[i] * qv[j];
        }
        __syncthreads();
    }
    float* sp = spart + ((size_t)split * NB * NHEADS + bh) * (SDIM * SDIM);
    #pragma unroll
    for (int i = 0; i < 3; i++)
        #pragma unroll
        for (int j = 0; j < 3; j++)
            sp[(si0 + i) * SDIM + (qi0 + j)] = acc[i][j];
}

// ---------------- 5) reduce partials + softmax over q (axis=-1) --------------
__global__ void softmax_kernel(const float* __restrict__ spart,
                               const float* __restrict__ alpha,
                               float* __restrict__ att)
{
    __shared__ float S[SDIM * SDIM];
    int bh = blockIdx.x;
    int tid = threadIdx.x;
    for (int e = tid; e < SDIM * SDIM; e += blockDim.x) {
        float s = 0.f;
        for (int sp = 0; sp < NSPLIT; sp++)
            s += spart[((size_t)sp * NB * NHEADS + bh) * (SDIM * SDIM) + e];
        S[e] = s;
    }
    __syncthreads();
    float inva = 1.0f / __ldg(alpha);
    if (tid < SDIM) {
        float m = -1e30f;
        for (int q = 0; q < SDIM; q++) m = fmaxf(m, S[tid * SDIM + q] * inva);
        float sum = 0.f;
        for (int q = 0; q < SDIM; q++) {
            float e = expf(S[tid * SDIM + q] * inva - m);
            S[tid * SDIM + q] = e;
            sum += e;
        }
        float r = 1.0f / sum;
        for (int q = 0; q < SDIM; q++)
            att[(size_t)bh * SDIM * SDIM + tid * SDIM + q] = S[tid * SDIM + q] * r;
    }
}

// ---------------- 6) apply attention: oc[q,pix] = sum_s V[s,pix]*att[s,q] ----
__global__ __launch_bounds__(128)
void av_kernel(const float* __restrict__ V, const float* __restrict__ att_g,
               float* __restrict__ out)
{
    __shared__ float att[SDIM][SDIM];
    int bh = blockIdx.y;
    int b = bh >> 2, hd = bh & 3;
    int tid = threadIdx.x;
    for (int l = tid; l < SDIM * SDIM; l += 128)
        att[l / SDIM][l % SDIM] = att_g[(size_t)bh * SDIM * SDIM + l];
    __syncthreads();

    int p = blockIdx.x * 128 + tid;
    size_t cbase = (size_t)b * NC * HWP + (size_t)hd * SDIM * HWP + p;

    float acc[SDIM];
    #pragma unroll
    for (int q = 0; q < SDIM; q++) acc[q] = 0.f;

    for (int s = 0; s < SDIM; s++) {
        float v = V[cbase + (size_t)s * HWP];
        const float4* a4 = reinterpret_cast<const float4*>(&att[s][0]);
        #pragma unroll
        for (int j = 0; j < 12; j++) {
            float4 a = a4[j];
            acc[4 * j + 0] += v * a.x;
            acc[4 * j + 1] += v * a.y;
            acc[4 * j + 2] += v * a.z;
            acc[4 * j + 3] += v * a.w;
        }
    }
    #pragma unroll
    for (int q = 0; q < SDIM; q++)
        out[cbase + (size_t)q * HWP] = acc[q];
}

// ---------------- 8) spatial transpose + residual: y[i,j]=z[j,i]+xn[i,j] -----
__global__ void trans_add_kernel(const float* __restrict__ z,
                                 const float* __restrict__ xn,
                                 float* __restrict__ y)
{
    __shared__ float tile[32][33];
    int plane = blockIdx.z;
    size_t base = (size_t)plane * HWP;
    int i0 = blockIdx.x * 32, j0 = blockIdx.y * 32;
    int tx = threadIdx.x, ty = threadIdx.y;
    for (int r = ty; r < 32; r += 8)
        tile[r][tx] = z[base + (size_t)(j0 + r) * NW + i0 + tx];
    __syncthreads();
    for (int r = ty; r < 32; r += 8) {
        size_t oidx = base + (size_t)(i0 + r) * NW + j0 + tx;
        y[oidx] = tile[tx][r] + xn[oidx];
    }
}

// ---------------- launch ------------------------------------------------------
extern "C" void kernel_launch(void* const* d_in, const int* in_sizes, int n_in,
                              void* d_out, int out_size)
{
    const float* x    = (const float*)d_in[0];
    const float* ln_w = (const float*)d_in[1];
    const float* ln_b = (const float*)d_in[2];
    const float* qpw  = (const float*)d_in[3];
    const float* qpb  = (const float*)d_in[4];
    const float* qdw  = (const float*)d_in[5];
    const float* qdb  = (const float*)d_in[6];
    const float* kpw  = (const float*)d_in[7];
    const float* kpb  = (const float*)d_in[8];
    const float* kdw  = (const float*)d_in[9];
    const float* kdb  = (const float*)d_in[10];
    const float* vpw  = (const float*)d_in[11];
    const float* vpb  = (const float*)d_in[12];
    const float* vdw  = (const float*)d_in[13];
    const float* vdb  = (const float*)d_in[14];
    const float* fw   = (const float*)d_in[15];
    const float* fb   = (const float*)d_in[16];
    const float* alpha= (const float*)d_in[17];
    float* y = (float*)d_out;

    float *p_xn, *p_qp, *p_kp, *p_vp, *p_q, *p_k, *p_v, *p_oc, *p_z, *p_sp, *p_att;
    cudaGetSymbolAddress((void**)&p_xn, g_xn);
    cudaGetSymbolAddress((void**)&p_qp, g_qp);
    cudaGetSymbolAddress((void**)&p_kp, g_kp);
    cudaGetSymbolAddress((void**)&p_vp, g_vp);
    cudaGetSymbolAddress((void**)&p_q,  g_q);
    cudaGetSymbolAddress((void**)&p_k,  g_k);
    cudaGetSymbolAddress((void**)&p_v,  g_v);
    cudaGetSymbolAddress((void**)&p_oc, g_oc);
    cudaGetSymbolAddress((void**)&p_z,  g_z);
    cudaGetSymbolAddress((void**)&p_sp, g_spart);
    cudaGetSymbolAddress((void**)&p_att,g_att);

    // 1) LayerNorm (fp32, residual-critical)
    ln_kernel<<<NPIX / 256, 256>>>(x, ln_w, ln_b, p_xn);

    // 2) QKV pointwise (fused: B tile loaded once for 3 weight sets)
    {
        dim3 grid(HWP / 64, NC / 64, NB);
        pw_gemm_kernel<3><<<grid, 256>>>(p_xn,
                                         qpw, qpb, p_qp,
                                         kpw, kpb, p_kp,
                                         vpw, vpb, p_vp);
    }

    // 3) depthwise 3x3 + bias (all three)
    {
        dim3 grid(HWP / 256, NB * NC);
        dw3_kernel<<<grid, 256>>>(p_qp, p_kp, p_vp,
                                  qdw, qdb, kdw, kdb, vdw, vdb,
                                  p_q, p_k, p_v);
    }

    // 4) S = K^T Q partials (deterministic split reduction)
    {
        dim3 grid(NSPLIT, NB * NHEADS);
        spart_kernel<<<grid, 256>>>(p_k, p_q, p_sp);
    }

    // 5) reduce + softmax over q
    softmax_kernel<<<NB * NHEADS, 256>>>(p_sp, alpha, p_att);

    // 6) out = V @ att
    {
        dim3 grid(HWP / 128, NB * NHEADS);
        av_kernel<<<grid, 128>>>(p_v, p_att, p_oc);
    }

    // 7) final pointwise conv: z = f_w @ oc + f_b (conv layout)
    {
        dim3 grid(HWP / 64, NC / 64, NB);
        pw_gemm_kernel<1><<<grid, 256>>>(p_oc,
                                         fw, fb, p_z,
                                         fw, fb, p_z,
                                         fw, fb, p_z);
    }

    // 8) spatial transpose (torch reshape quirk) + residual
    {
        dim3 grid(NW / 32, NH / 32, NB * NC);
        trans_add_kernel<<<grid, dim3(32, 8)>>>(p_z, p_xn, y);
    }
}

// round 6
// speedup vs baseline: 1.0086x; 1.0086x over previous
#include <cuda_runtime.h>
#include <cuda_bf16.h>
#include <cstdint>

#define NB 8
#define NC 192
#define NH 128
#define NW 128
#define HWP (NH*NW)            // 16384 pixels per plane
#define NPIX (NB*HWP)          // 131072
#define NELEM ((size_t)NB*NC*HWP) // 25,165,824
#define NHEADS 4
#define SDIM 48                // channels per head
#define NSPLIT 64              // t-splits for K^T Q reduction

// ---------------- scratch (device globals; no runtime allocation) -------------
__device__ float g_xn[NB*NC*HWP];
__device__ float g_qp[NB*NC*HWP];
__device__ float g_kp[NB*NC*HWP];
__device__ float g_vp[NB*NC*HWP];
__device__ float g_q [NB*NC*HWP];
__device__ float g_k [NB*NC*HWP];
__device__ float g_v [NB*NC*HWP];
__device__ float g_oc[NB*NC*HWP];
__device__ float g_z [NB*NC*HWP];
__device__ float g_spart[(size_t)NSPLIT*NB*NHEADS*SDIM*SDIM];
__device__ float g_att[(size_t)NB*NHEADS*SDIM*SDIM];

// ---------------- 1) channel LayerNorm (per pixel over C=192), fp32 ----------
__global__ void ln_kernel(const float* __restrict__ x,
                          const float* __restrict__ lw,
                          const float* __restrict__ lb,
                          float* __restrict__ xn)
{
    int pix = blockIdx.x * blockDim.x + threadIdx.x;   // 0..NPIX-1
    int b = pix / HWP;
    int p = pix - b * HWP;
    const float* xb = x + (size_t)b * NC * HWP + p;
    float s = 0.f, s2 = 0.f;
    #pragma unroll 4
    for (int c = 0; c < NC; c++) {
        float v = __ldg(xb + (size_t)c * HWP);
        s += v; s2 += v * v;
    }
    const float inv_c = 1.0f / NC;
    float mu = s * inv_c;
    float var = s2 * inv_c - mu * mu;
    float rstd = rsqrtf(var + 1e-5f);
    float* ob = xn + (size_t)b * NC * HWP + p;
    #pragma unroll 4
    for (int c = 0; c < NC; c++) {
        float v = __ldg(xb + (size_t)c * HWP);
        ob[(size_t)c * HWP] = (v - mu) * rstd * __ldg(lw + c) + __ldg(lb + c);
    }
}

// ---------------- 2) pointwise 1x1 conv GEMM (NSETS weight sets share B) -----
// out[set][b, oc, p] = sum_c W[set][oc,c] * xin[b,c,p] + bias[set][oc]
// BM=64 oc, BN=64 pixels, BK=16, 256 threads, 4x4 micro-tile per set.
template<int NSETS>
__global__ __launch_bounds__(256)
void pw_gemm_kernel(const float* __restrict__ xin,
                    const float* __restrict__ w0, const float* __restrict__ bb0, float* __restrict__ o0,
                    const float* __restrict__ w1, const float* __restrict__ bb1, float* __restrict__ o1,
                    const float* __restrict__ w2, const float* __restrict__ bb2, float* __restrict__ o2)
{
    __shared__ float As[NSETS][16][65];
    __shared__ float Bs[16][64];

    const int tid = threadIdx.x;
    const int tx = tid & 15;
    const int ty = tid >> 4;
    const int p0  = blockIdx.x * 64;
    const int oc0 = blockIdx.y * 64;
    const size_t bbase = (size_t)blockIdx.z * NC * HWP;

    const float* wptr[3]  = { w0, w1, w2 };
    const float* bptr[3]  = { bb0, bb1, bb2 };
    float*       optr[3]  = { o0, o1, o2 };

    float acc[NSETS][4][4];
    #pragma unroll
    for (int s = 0; s < NSETS; s++)
        #pragma unroll
        for (int i = 0; i < 4; i++)
            #pragma unroll
            for (int j = 0; j < 4; j++)
                acc[s][i][j] = 0.f;

    for (int k0 = 0; k0 < NC; k0 += 16) {
        // load B tile (xn): 16 x 64
        #pragma unroll
        for (int m = 0; m < 4; m++) {
            int idx = tid + 256 * m;
            int kk = idx >> 6, p = idx & 63;
            Bs[kk][p] = xin[bbase + (size_t)(k0 + kk) * HWP + p0 + p];
        }
        // load A tiles (weights), transposed into [k][oc]
        #pragma unroll
        for (int s = 0; s < NSETS; s++) {
            const float* w = wptr[s];
            #pragma unroll
            for (int m = 0; m < 4; m++) {
                int idx = tid + 256 * m;
                int oc = idx >> 4, kk = idx & 15;
                As[s][kk][oc] = __ldg(w + (size_t)(oc0 + oc) * NC + k0 + kk);
            }
        }
        __syncthreads();

        #pragma unroll
        for (int k = 0; k < 16; k++) {
            float bv[4];
            #pragma unroll
            for (int j = 0; j < 4; j++) bv[j] = Bs[k][tx + 16 * j];
            #pragma unroll
            for (int s = 0; s < NSETS; s++) {
                float av[4];
                #pragma unroll
                for (int i = 0; i < 4; i++) av[i] = As[s][k][ty + 16 * i];
                #pragma unroll
                for (int i = 0; i < 4; i++)
                    #pragma unroll
                    for (int j = 0; j < 4; j++)
                        acc[s][i][j] += av[i] * bv[j];
            }
        }
        __syncthreads();
    }

    #pragma unroll
    for (int s = 0; s < NSETS; s++) {
        #pragma unroll
        for (int i = 0; i < 4; i++) {
            int oc = oc0 + ty + 16 * i;
            float bsv = __ldg(bptr[s] + oc);
            #pragma unroll
            for (int j = 0; j < 4; j++) {
                int p = p0 + tx + 16 * j;
                optr[s][bbase + (size_t)oc * HWP + p] = acc[s][i][j] + bsv;
            }
        }
    }
}

// ---------------- 3) depthwise 3x3 SAME conv + bias (3 tensors fused) --------
__global__ void dw3_kernel(const float* __restrict__ qp, const float* __restrict__ kp, const float* __restrict__ vp,
                           const float* __restrict__ qdw, const float* __restrict__ qdb,
                           const float* __restrict__ kdw, const float* __restrict__ kdb,
                           const float* __restrict__ vdw, const float* __restrict__ vdb,
                           float* __restrict__ qo, float* __restrict__ ko, float* __restrict__ vo)
{
    int plane = blockIdx.y;              // b*NC + c
    int c = plane % NC;
    int p = blockIdx.x * blockDim.x + threadIdx.x;   // 0..HWP-1
    int h = p >> 7, w = p & 127;
    size_t base = (size_t)plane * HWP;

    float aq = __ldg(qdb + c), ak = __ldg(kdb + c), av = __ldg(vdb + c);
    #pragma unroll
    for (int kh = 0; kh < 3; kh++) {
        int hh = h + kh - 1;
        if ((unsigned)hh >= NH) continue;
        #pragma unroll
        for (int kw = 0; kw < 3; kw++) {
            int ww = w + kw - 1;
            if ((unsigned)ww >= NW) continue;
            size_t idx = base + (size_t)hh * NW + ww;
            int wi = c * 9 + kh * 3 + kw;
            aq += __ldg(qp + idx) * __ldg(qdw + wi);
            ak += __ldg(kp + idx) * __ldg(kdw + wi);
            av += __ldg(vp + idx) * __ldg(vdw + wi);
        }
    }
    qo[base + p] = aq;
    ko[base + p] = ak;
    vo[base + p] = av;
}

// ---------------- 4) S partials: S[s,q] = sum_pix K[.,s]*Q[.,q] --------------
// grid.x = NSPLIT (t-splits), grid.y = NB*NHEADS; 256 threads map 16x16 -> 3x3
__global__ __launch_bounds__(256)
void spart_kernel(const float* __restrict__ K, const float* __restrict__ Q,
                  float* __restrict__ spart)
{
    __shared__ float Ks[SDIM][33];
    __shared__ float Qs[SDIM][33];
    int split = blockIdx.x;
    int bh = blockIdx.y;
    int b = bh >> 2, hd = bh & 3;
    size_t cbase = (size_t)b * NC * HWP + (size_t)hd * SDIM * HWP;
    int p0 = split * (HWP / NSPLIT);      // 256 pixels per block

    int tid = threadIdx.x;
    int si0 = (tid >> 4) * 3;
    int qi0 = (tid & 15) * 3;

    float acc[3][3] = {};
    for (int ch = 0; ch < (HWP / NSPLIT) / 32; ch++) {
        int pp = p0 + ch * 32;
        for (int l = tid; l < SDIM * 32; l += 256) {
            int cc = l >> 5, t = l & 31;
            Ks[cc][t] = K[cbase + (size_t)cc * HWP + pp + t];
            Qs[cc][t] = Q[cbase + (size_t)cc * HWP + pp + t];
        }
        __syncthreads();
        #pragma unroll 4
        for (int t = 0; t < 32; t++) {
            float kv[3], qv[3];
            #pragma unroll
            for (int i = 0; i < 3; i++) { kv[i] = Ks[si0 + i][t]; qv[i] = Qs[qi0 + i][t]; }
            #pragma unroll
            for (int i = 0; i < 3; i++)
                #pragma unroll
                for (int j = 0; j < 3; j++)
                    acc[i][j] += kv[i] * qv[j];
        }
        __syncthreads();
    }
    float* sp = spart + ((size_t)split * NB * NHEADS + bh) * (SDIM * SDIM);
    #pragma unroll
    for (int i = 0; i < 3; i++)
        #pragma unroll
        for (int j = 0; j < 3; j++)
            sp[(si0 + i) * SDIM + (qi0 + j)] = acc[i][j];
}

// ---------------- 5) reduce partials + softmax over q (axis=-1) --------------
__global__ void softmax_kernel(const float* __restrict__ spart,
                               const float* __restrict__ alpha,
                               float* __restrict__ att)
{
    __shared__ float S[SDIM * SDIM];
    int bh = blockIdx.x;
    int tid = threadIdx.x;
    for (int e = tid; e < SDIM * SDIM; e += blockDim.x) {
        float s = 0.f;
        for (int sp = 0; sp < NSPLIT; sp++)
            s += spart[((size_t)sp * NB * NHEADS + bh) * (SDIM * SDIM) + e];
        S[e] = s;
    }
    __syncthreads();
    float inva = 1.0f / __ldg(alpha);
    if (tid < SDIM) {
        float m = -1e30f;
        for (int q = 0; q < SDIM; q++) m = fmaxf(m, S[tid * SDIM + q] * inva);
        float sum = 0.f;
        for (int q = 0; q < SDIM; q++) {
            float e = expf(S[tid * SDIM + q] * inva - m);
            S[tid * SDIM + q] = e;
            sum += e;
        }
        float r = 1.0f / sum;
        for (int q = 0; q < SDIM; q++)
            att[(size_t)bh * SDIM * SDIM + tid * SDIM + q] = S[tid * SDIM + q] * r;
    }
}

// ---------------- 6) apply attention: oc[q,pix] = sum_s V[s,pix]*att[s,q] ----
__global__ __launch_bounds__(128)
void av_kernel(const float* __restrict__ V, const float* __restrict__ att_g,
               float* __restrict__ out)
{
    __shared__ float att[SDIM][SDIM];
    int bh = blockIdx.y;
    int b = bh >> 2, hd = bh & 3;
    int tid = threadIdx.x;
    for (int l = tid; l < SDIM * SDIM; l += 128)
        att[l / SDIM][l % SDIM] = att_g[(size_t)bh * SDIM * SDIM + l];
    __syncthreads();

    int p = blockIdx.x * 128 + tid;
    size_t cbase = (size_t)b * NC * HWP + (size_t)hd * SDIM * HWP + p;

    float acc[SDIM];
    #pragma unroll
    for (int q = 0; q < SDIM; q++) acc[q] = 0.f;

    for (int s = 0; s < SDIM; s++) {
        float v = V[cbase + (size_t)s * HWP];
        const float4* a4 = reinterpret_cast<const float4*>(&att[s][0]);
        #pragma unroll
        for (int j = 0; j < 12; j++) {
            float4 a = a4[j];
            acc[4 * j + 0] += v * a.x;
            acc[4 * j + 1] += v * a.y;
            acc[4 * j + 2] += v * a.z;
            acc[4 * j + 3] += v * a.w;
        }
    }
    #pragma unroll
    for (int q = 0; q < SDIM; q++)
        out[cbase + (size_t)q * HWP] = acc[q];
}

// ---------------- 8) spatial transpose + residual: y[i,j]=z[j,i]+xn[i,j] -----
__global__ void trans_add_kernel(const float* __restrict__ z,
                                 const float* __restrict__ xn,
                                 float* __restrict__ y)
{
    __shared__ float tile[32][33];
    int plane = blockIdx.z;
    size_t base = (size_t)plane * HWP;
    int i0 = blockIdx.x * 32, j0 = blockIdx.y * 32;
    int tx = threadIdx.x, ty = threadIdx.y;
    for (int r = ty; r < 32; r += 8)
        tile[r][tx] = z[base + (size_t)(j0 + r) * NW + i0 + tx];
    __syncthreads();
    for (int r = ty; r < 32; r += 8) {
        size_t oidx = base + (size_t)(i0 + r) * NW + j0 + tx;
        y[oidx] = tile[tx][r] + xn[oidx];
    }
}

// ---------------- launch ------------------------------------------------------
extern "C" void kernel_launch(void* const* d_in, const int* in_sizes, int n_in,
                              void* d_out, int out_size)
{
    const float* x    = (const float*)d_in[0];
    const float* ln_w = (const float*)d_in[1];
    const float* ln_b = (const float*)d_in[2];
    const float* qpw  = (const float*)d_in[3];
    const float* qpb  = (const float*)d_in[4];
    const float* qdw  = (const float*)d_in[5];
    const float* qdb  = (const float*)d_in[6];
    const float* kpw  = (const float*)d_in[7];
    const float* kpb  = (const float*)d_in[8];
    const float* kdw  = (const float*)d_in[9];
    const float* kdb  = (const float*)d_in[10];
    const float* vpw  = (const float*)d_in[11];
    const float* vpb  = (const float*)d_in[12];
    const float* vdw  = (const float*)d_in[13];
    const float* vdb  = (const float*)d_in[14];
    const float* fw   = (const float*)d_in[15];
    const float* fb   = (const float*)d_in[16];
    const float* alpha= (const float*)d_in[17];
    float* y = (float*)d_out;

    float *p_xn, *p_qp, *p_kp, *p_vp, *p_q, *p_k, *p_v, *p_oc, *p_z, *p_sp, *p_att;
    cudaGetSymbolAddress((void**)&p_xn, g_xn);
    cudaGetSymbolAddress((void**)&p_qp, g_qp);
    cudaGetSymbolAddress((void**)&p_kp, g_kp);
    cudaGetSymbolAddress((void**)&p_vp, g_vp);
    cudaGetSymbolAddress((void**)&p_q,  g_q);
    cudaGetSymbolAddress((void**)&p_k,  g_k);
    cudaGetSymbolAddress((void**)&p_v,  g_v);
    cudaGetSymbolAddress((void**)&p_oc, g_oc);
    cudaGetSymbolAddress((void**)&p_z,  g_z);
    cudaGetSymbolAddress((void**)&p_sp, g_spart);
    cudaGetSymbolAddress((void**)&p_att,g_att);

    // 1) LayerNorm (fp32, residual-critical)
    ln_kernel<<<NPIX / 256, 256>>>(x, ln_w, ln_b, p_xn);

    // 2) QKV pointwise (fused: B tile loaded once for 3 weight sets)
    {
        dim3 grid(HWP / 64, NC / 64, NB);
        pw_gemm_kernel<3><<<grid, 256>>>(p_xn,
                                         qpw, qpb, p_qp,
                                         kpw, kpb, p_kp,
                                         vpw, vpb, p_vp);
    }

    // 3) depthwise 3x3 + bias (all three)
    {
        dim3 grid(HWP / 256, NB * NC);
        dw3_kernel<<<grid, 256>>>(p_qp, p_kp, p_vp,
                                  qdw, qdb, kdw, kdb, vdw, vdb,
                                  p_q, p_k, p_v);
    }

    // 4) S = K^T Q partials (deterministic split reduction)
    {
        dim3 grid(NSPLIT, NB * NHEADS);
        spart_kernel<<<grid, 256>>>(p_k, p_q, p_sp);
    }

    // 5) reduce + softmax over q
    softmax_kernel<<<NB * NHEADS, 256>>>(p_sp, alpha, p_att);

    // 6) out = V @ att
    {
        dim3 grid(HWP / 128, NB * NHEADS);
        av_kernel<<<grid, 128>>>(p_v, p_att, p_oc);
    }

    // 7) final pointwise conv: z = f_w @ oc + f_b (conv layout)
    {
        dim3 grid(HWP / 64, NC / 64, NB);
        pw_gemm_kernel<1><<<grid, 256>>>(p_oc,
                                         fw, fb, p_z,
                                         fw, fb, p_z,
                                         fw, fb, p_z);
    }

    // 8) spatial transpose (torch reshape quirk) + residual
    {
        dim3 grid(NW / 32, NH / 32, NB * NC);
        trans_add_kernel<<<grid, dim3(32, 8)>>>(p_z, p_xn, y);
    }
}

// round 7
// speedup vs baseline: 1.0091x; 1.0005x over previous
#include <cuda_runtime.h>
#include <cuda_bf16.h>
#include <cstdint>

#define NB 8
#define NC 192
#define NH 128
#define NW 128
#define HWP (NH*NW)            // 16384 pixels per plane
#define NPIX (NB*HWP)          // 131072
#define NELEM ((size_t)NB*NC*HWP) // 25,165,824
#define NHEADS 4
#define SDIM 48                // channels per head
#define NSPLIT 64              // t-splits for K^T Q reduction

// ---------------- scratch (device globals; no runtime allocation) -------------
__device__ float g_xn[NB*NC*HWP];
__device__ float g_qp[NB*NC*HWP];
__device__ float g_kp[NB*NC*HWP];
__device__ float g_vp[NB*NC*HWP];
__device__ float g_q [NB*NC*HWP];
__device__ float g_k [NB*NC*HWP];
__device__ float g_v [NB*NC*HWP];
__device__ float g_oc[NB*NC*HWP];
__device__ float g_z [NB*NC*HWP];
__device__ float g_spart[(size_t)NSPLIT*NB*NHEADS*SDIM*SDIM];
__device__ float g_att[(size_t)NB*NHEADS*SDIM*SDIM];

// ---------------- 1) channel LayerNorm (per pixel over C=192), fp32 ----------
__global__ void ln_kernel(const float* __restrict__ x,
                          const float* __restrict__ lw,
                          const float* __restrict__ lb,
                          float* __restrict__ xn)
{
    int pix = blockIdx.x * blockDim.x + threadIdx.x;   // 0..NPIX-1
    int b = pix / HWP;
    int p = pix - b * HWP;
    const float* xb = x + (size_t)b * NC * HWP + p;
    float s = 0.f, s2 = 0.f;
    #pragma unroll 4
    for (int c = 0; c < NC; c++) {
        float v = __ldg(xb + (size_t)c * HWP);
        s += v; s2 += v * v;
    }
    const float inv_c = 1.0f / NC;
    float mu = s * inv_c;
    float var = s2 * inv_c - mu * mu;
    float rstd = rsqrtf(var + 1e-5f);
    float* ob = xn + (size_t)b * NC * HWP + p;
    #pragma unroll 4
    for (int c = 0; c < NC; c++) {
        float v = __ldg(xb + (size_t)c * HWP);
        ob[(size_t)c * HWP] = (v - mu) * rstd * __ldg(lw + c) + __ldg(lb + c);
    }
}

// ---------------- 2) pointwise 1x1 conv GEMM (NSETS weight sets share B) -----
// out[set][b, oc, p] = sum_c W[set][oc,c] * xin[b,c,p] + bias[set][oc]
// BM=64 oc, BN=64 pixels, BK=16, 256 threads, 4x4 micro-tile per set.
template<int NSETS>
__global__ __launch_bounds__(256)
void pw_gemm_kernel(const float* __restrict__ xin,
                    const float* __restrict__ w0, const float* __restrict__ bb0, float* __restrict__ o0,
                    const float* __restrict__ w1, const float* __restrict__ bb1, float* __restrict__ o1,
                    const float* __restrict__ w2, const float* __restrict__ bb2, float* __restrict__ o2)
{
    __shared__ float As[NSETS][16][65];
    __shared__ float Bs[16][64];

    const int tid = threadIdx.x;
    const int tx = tid & 15;
    const int ty = tid >> 4;
    const int p0  = blockIdx.x * 64;
    const int oc0 = blockIdx.y * 64;
    const size_t bbase = (size_t)blockIdx.z * NC * HWP;

    const float* wptr[3]  = { w0, w1, w2 };
    const float* bptr[3]  = { bb0, bb1, bb2 };
    float*       optr[3]  = { o0, o1, o2 };

    float acc[NSETS][4][4];
    #pragma unroll
    for (int s = 0; s < NSETS; s++)
        #pragma unroll
        for (int i = 0; i < 4; i++)
            #pragma unroll
            for (int j = 0; j < 4; j++)
                acc[s][i][j] = 0.f;

    for (int k0 = 0; k0 < NC; k0 += 16) {
        // load B tile (xn): 16 x 64
        #pragma unroll
        for (int m = 0; m < 4; m++) {
            int idx = tid + 256 * m;
            int kk = idx >> 6, p = idx & 63;
            Bs[kk][p] = xin[bbase + (size_t)(k0 + kk) * HWP + p0 + p];
        }
        // load A tiles (weights), transposed into [k][oc]
        #pragma unroll
        for (int s = 0; s < NSETS; s++) {
            const float* w = wptr[s];
            #pragma unroll
            for (int m = 0; m < 4; m++) {
                int idx = tid + 256 * m;
                int oc = idx >> 4, kk = idx & 15;
                As[s][kk][oc] = __ldg(w + (size_t)(oc0 + oc) * NC + k0 + kk);
            }
        }
        __syncthreads();

        #pragma unroll
        for (int k = 0; k < 16; k++) {
            float bv[4];
            #pragma unroll
            for (int j = 0; j < 4; j++) bv[j] = Bs[k][tx + 16 * j];
            #pragma unroll
            for (int s = 0; s < NSETS; s++) {
                float av[4];
                #pragma unroll
                for (int i = 0; i < 4; i++) av[i] = As[s][k][ty + 16 * i];
                #pragma unroll
                for (int i = 0; i < 4; i++)
                    #pragma unroll
                    for (int j = 0; j < 4; j++)
                        acc[s][i][j] += av[i] * bv[j];
            }
        }
        __syncthreads();
    }

    #pragma unroll
    for (int s = 0; s < NSETS; s++) {
        #pragma unroll
        for (int i = 0; i < 4; i++) {
            int oc = oc0 + ty + 16 * i;
            float bsv = __ldg(bptr[s] + oc);
            #pragma unroll
            for (int j = 0; j < 4; j++) {
                int p = p0 + tx + 16 * j;
                optr[s][bbase + (size_t)oc * HWP + p] = acc[s][i][j] + bsv;
            }
        }
    }
}

// ---------------- 3) depthwise 3x3 SAME conv + bias (3 tensors fused) --------
__global__ void dw3_kernel(const float* __restrict__ qp, const float* __restrict__ kp, const float* __restrict__ vp,
                           const float* __restrict__ qdw, const float* __restrict__ qdb,
                           const float* __restrict__ kdw, const float* __restrict__ kdb,
                           const float* __restrict__ vdw, const float* __restrict__ vdb,
                           float* __restrict__ qo, float* __restrict__ ko, float* __restrict__ vo)
{
    int plane = blockIdx.y;              // b*NC + c
    int c = plane % NC;
    int p = blockIdx.x * blockDim.x + threadIdx.x;   // 0..HWP-1
    int h = p >> 7, w = p & 127;
    size_t base = (size_t)plane * HWP;

    float aq = __ldg(qdb + c), ak = __ldg(kdb + c), av = __ldg(vdb + c);
    #pragma unroll
    for (int kh = 0; kh < 3; kh++) {
        int hh = h + kh - 1;
        if ((unsigned)hh >= NH) continue;
        #pragma unroll
        for (int kw = 0; kw < 3; kw++) {
            int ww = w + kw - 1;
            if ((unsigned)ww >= NW) continue;
            size_t idx = base + (size_t)hh * NW + ww;
            int wi = c * 9 + kh * 3 + kw;
            aq += __ldg(qp + idx) * __ldg(qdw + wi);
            ak += __ldg(kp + idx) * __ldg(kdw + wi);
            av += __ldg(vp + idx) * __ldg(vdw + wi);
        }
    }
    qo[base + p] = aq;
    ko[base + p] = ak;
    vo[base + p] = av;
}

// ---------------- 4) S partials: S[s,q] = sum_pix K[.,s]*Q[.,q] --------------
// grid.x = NSPLIT (t-splits), grid.y = NB*NHEADS; 256 threads map 16x16 -> 3x3
__global__ __launch_bounds__(256)
void spart_kernel(const float* __restrict__ K, const float* __restrict__ Q,
                  float* __restrict__ spart)
{
    __shared__ float Ks[SDIM][33];
    __shared__ float Qs[SDIM][33];
    int split = blockIdx.x;
    int bh = blockIdx.y;
    int b = bh >> 2, hd = bh & 3;
    size_t cbase = (size_t)b * NC * HWP + (size_t)hd * SDIM * HWP;
    int p0 = split * (HWP / NSPLIT);      // 256 pixels per block

    int tid = threadIdx.x;
    int si0 = (tid >> 4) * 3;
    int qi0 = (tid & 15) * 3;

    float acc[3][3] = {};
    for (int ch = 0; ch < (HWP / NSPLIT) / 32; ch++) {
        int pp = p0 + ch * 32;
        for (int l = tid; l < SDIM * 32; l += 256) {
            int cc = l >> 5, t = l & 31;
            Ks[cc][t] = K[cbase + (size_t)cc * HWP + pp + t];
            Qs[cc][t] = Q[cbase + (size_t)cc * HWP + pp + t];
        }
        __syncthreads();
        #pragma unroll 4
        for (int t = 0; t < 32; t++) {
            float kv[3], qv[3];
            #pragma unroll
            for (int i = 0; i < 3; i++) { kv[i] = Ks[si0 + i][t]; qv[i] = Qs[qi0 + i][t]; }
            #pragma unroll
            for (int i = 0; i < 3; i++)
                #pragma unroll
                for (int j = 0; j < 3; j++)
                    acc[i][j] += kv[i] * qv[j];
        }
        __syncthreads();
    }
    float* sp = spart + ((size_t)split * NB * NHEADS + bh) * (SDIM * SDIM);
    #pragma unroll
    for (int i = 0; i < 3; i++)
        #pragma unroll
        for (int j = 0; j < 3; j++)
            sp[(si0 + i) * SDIM + (qi0 + j)] = acc[i][j];
}

// ---------------- 5) reduce partials + softmax over q (axis=-1) --------------
__global__ void softmax_kernel(const float* __restrict__ spart,
                               const float* __restrict__ alpha,
                               float* __restrict__ att)
{
    __shared__ float S[SDIM * SDIM];
    int bh = blockIdx.x;
    int tid = threadIdx.x;
    for (int e = tid; e < SDIM * SDIM; e += blockDim.x) {
        float s = 0.f;
        for (int sp = 0; sp < NSPLIT; sp++)
            s += spart[((size_t)sp * NB * NHEADS + bh) * (SDIM * SDIM) + e];
        S[e] = s;
    }
    __syncthreads();
    float inva = 1.0f / __ldg(alpha);
    if (tid < SDIM) {
        float m = -1e30f;
        for (int q = 0; q < SDIM; q++) m = fmaxf(m, S[tid * SDIM + q] * inva);
        float sum = 0.f;
        for (int q = 0; q < SDIM; q++) {
            float e = expf(S[tid * SDIM + q] * inva - m);
            S[tid * SDIM + q] = e;
            sum += e;
        }
        float r = 1.0f / sum;
        for (int q = 0; q < SDIM; q++)
            att[(size_t)bh * SDIM * SDIM + tid * SDIM + q] = S[tid * SDIM + q] * r;
    }
}

// ---------------- 6) apply attention: oc[q,pix] = sum_s V[s,pix]*att[s,q] ----
__global__ __launch_bounds__(128)
void av_kernel(const float* __restrict__ V, const float* __restrict__ att_g,
               float* __restrict__ out)
{
    __shared__ float att[SDIM][SDIM];
    int bh = blockIdx.y;
    int b = bh >> 2, hd = bh & 3;
    int tid = threadIdx.x;
    for (int l = tid; l < SDIM * SDIM; l += 128)
        att[l / SDIM][l % SDIM] = att_g[(size_t)bh * SDIM * SDIM + l];
    __syncthreads();

    int p = blockIdx.x * 128 + tid;
    size_t cbase = (size_t)b * NC * HWP + (size_t)hd * SDIM * HWP + p;

    float acc[SDIM];
    #pragma unroll
    for (int q = 0; q < SDIM; q++) acc[q] = 0.f;

    for (int s = 0; s < SDIM; s++) {
        float v = V[cbase + (size_t)s * HWP];
        const float4* a4 = reinterpret_cast<const float4*>(&att[s][0]);
        #pragma unroll
        for (int j = 0; j < 12; j++) {
            float4 a = a4[j];
            acc[4 * j + 0] += v * a.x;
            acc[4 * j + 1] += v * a.y;
            acc[4 * j + 2] += v * a.z;
            acc[4 * j + 3] += v * a.w;
        }
    }
    #pragma unroll
    for (int q = 0; q < SDIM; q++)
        out[cbase + (size_t)q * HWP] = acc[q];
}

// ---------------- 8) spatial transpose + residual: y[i,j]=z[j,i]+xn[i,j] -----
__global__ void trans_add_kernel(const float* __restrict__ z,
                                 const float* __restrict__ xn,
                                 float* __restrict__ y)
{
    __shared__ float tile[32][33];
    int plane = blockIdx.z;
    size_t base = (size_t)plane * HWP;
    int i0 = blockIdx.x * 32, j0 = blockIdx.y * 32;
    int tx = threadIdx.x, ty = threadIdx.y;
    for (int r = ty; r < 32; r += 8)
        tile[r][tx] = z[base + (size_t)(j0 + r) * NW + i0 + tx];
    __syncthreads();
    for (int r = ty; r < 32; r += 8) {
        size_t oidx = base + (size_t)(i0 + r) * NW + j0 + tx;
        y[oidx] = tile[tx][r] + xn[oidx];
    }
}

// ---------------- launch ------------------------------------------------------
extern "C" void kernel_launch(void* const* d_in, const int* in_sizes, int n_in,
                              void* d_out, int out_size)
{
    const float* x    = (const float*)d_in[0];
    const float* ln_w = (const float*)d_in[1];
    const float* ln_b = (const float*)d_in[2];
    const float* qpw  = (const float*)d_in[3];
    const float* qpb  = (const float*)d_in[4];
    const float* qdw  = (const float*)d_in[5];
    const float* qdb  = (const float*)d_in[6];
    const float* kpw  = (const float*)d_in[7];
    const float* kpb  = (const float*)d_in[8];
    const float* kdw  = (const float*)d_in[9];
    const float* kdb  = (const float*)d_in[10];
    const float* vpw  = (const float*)d_in[11];
    const float* vpb  = (const float*)d_in[12];
    const float* vdw  = (const float*)d_in[13];
    const float* vdb  = (const float*)d_in[14];
    const float* fw   = (const float*)d_in[15];
    const float* fb   = (const float*)d_in[16];
    const float* alpha= (const float*)d_in[17];
    float* y = (float*)d_out;

    float *p_xn, *p_qp, *p_kp, *p_vp, *p_q, *p_k, *p_v, *p_oc, *p_z, *p_sp, *p_att;
    cudaGetSymbolAddress((void**)&p_xn, g_xn);
    cudaGetSymbolAddress((void**)&p_qp, g_qp);
    cudaGetSymbolAddress((void**)&p_kp, g_kp);
    cudaGetSymbolAddress((void**)&p_vp, g_vp);
    cudaGetSymbolAddress((void**)&p_q,  g_q);
    cudaGetSymbolAddress((void**)&p_k,  g_k);
    cudaGetSymbolAddress((void**)&p_v,  g_v);
    cudaGetSymbolAddress((void**)&p_oc, g_oc);
    cudaGetSymbolAddress((void**)&p_z,  g_z);
    cudaGetSymbolAddress((void**)&p_sp, g_spart);
    cudaGetSymbolAddress((void**)&p_att,g_att);

    // 1) LayerNorm (fp32, residual-critical)
    ln_kernel<<<NPIX / 256, 256>>>(x, ln_w, ln_b, p_xn);

    // 2) QKV pointwise (fused: B tile loaded once for 3 weight sets)
    {
        dim3 grid(HWP / 64, NC / 64, NB);
        pw_gemm_kernel<3><<<grid, 256>>>(p_xn,
                                         qpw, qpb, p_qp,
                                         kpw, kpb, p_kp,
                                         vpw, vpb, p_vp);
    }

    // 3) depthwise 3x3 + bias (all three)
    {
        dim3 grid(HWP / 256, NB * NC);
        dw3_kernel<<<grid, 256>>>(p_qp, p_kp, p_vp,
                                  qdw, qdb, kdw, kdb, vdw, vdb,
                                  p_q, p_k, p_v);
    }

    // 4) S = K^T Q partials (deterministic split reduction)
    {
        dim3 grid(NSPLIT, NB * NHEADS);
        spart_kernel<<<grid, 256>>>(p_k, p_q, p_sp);
    }

    // 5) reduce + softmax over q
    softmax_kernel<<<NB * NHEADS, 256>>>(p_sp, alpha, p_att);

    // 6) out = V @ att
    {
        dim3 grid(HWP / 128, NB * NHEADS);
        av_kernel<<<grid, 128>>>(p_v, p_att, p_oc);
    }

    // 7) final pointwise conv: z = f_w @ oc + f_b (conv layout)
    {
        dim3 grid(HWP / 64, NC / 64, NB);
        pw_gemm_kernel<1><<<grid, 256>>>(p_oc,
                                         fw, fb, p_z,
                                         fw, fb, p_z,
                                         fw, fb, p_z);
    }

    // 8) spatial transpose (torch reshape quirk) + residual
    {
        dim3 grid(NW / 32, NH / 32, NB * NC);
        trans_add_kernel<<<grid, dim3(32, 8)>>>(p_z, p_xn, y);
    }
}